// round 4
// baseline (speedup 1.0000x reference)
#include <cuda_runtime.h>

#define BB 16
#define CC 256
#define HH 128
#define WW 128
#define HW (HH*WW)      // 16384
#define HW4 (HW/4)      // 4096

// Scratch (no allocations allowed): reduced [B,2,H,W] and gate [B,H,W]
__device__ float g_red[BB * 2 * HW];
__device__ float g_gate[BB * HW];

// ---------------------------------------------------------------------------
// Kernel 1: channel max + mean. One thread per float4 of spatial positions.
// For a fixed channel c, the 32 threads of a warp read 512 contiguous bytes.
// ---------------------------------------------------------------------------
__global__ void __launch_bounds__(256) reduce_kernel(const float* __restrict__ x) {
    int idx = blockIdx.x * blockDim.x + threadIdx.x;   // 0 .. B*HW4-1 (65536)
    int b   = idx >> 12;                               // / 4096
    int hw4 = idx & (HW4 - 1);

    const float4* xb = reinterpret_cast<const float4*>(x)
                       + (size_t)b * CC * HW4 + hw4;

    float4 v0 = xb[0];
    float4 mx = v0;
    float4 sm = v0;

    #pragma unroll 8
    for (int c = 1; c < CC; ++c) {
        float4 v = xb[(size_t)c * HW4];
        mx.x = fmaxf(mx.x, v.x);  mx.y = fmaxf(mx.y, v.y);
        mx.z = fmaxf(mx.z, v.z);  mx.w = fmaxf(mx.w, v.w);
        sm.x += v.x;  sm.y += v.y;  sm.z += v.z;  sm.w += v.w;
    }

    const float inv = 1.0f / (float)CC;
    float4* mout = reinterpret_cast<float4*>(g_red) + (size_t)b * 2 * HW4 + hw4;
    float4* aout = mout + HW4;
    *mout = mx;
    *aout = make_float4(sm.x * inv, sm.y * inv, sm.z * inv, sm.w * inv);
}

// ---------------------------------------------------------------------------
// Kernel 2: 7x7 conv over [B,2,H,W] (channel 0 = max, 1 = avg) + hsigmoid.
// Inputs (2 MB) are L2-resident; weights broadcast via smem.
// ---------------------------------------------------------------------------
__global__ void __launch_bounds__(256) conv_kernel(const float* __restrict__ w,
                                                   const float* __restrict__ bias) {
    __shared__ float sw[98];
    __shared__ float sb;
    if (threadIdx.x < 98) sw[threadIdx.x] = w[threadIdx.x];
    if (threadIdx.x == 0) sb = bias[0];
    __syncthreads();

    int idx = blockIdx.x * blockDim.x + threadIdx.x;   // 0 .. B*HW-1
    int b   = idx >> 14;
    int hw  = idx & (HW - 1);
    int h   = hw >> 7;
    int wq  = hw & (WW - 1);

    const float* mp = g_red + (size_t)b * 2 * HW;   // max plane
    const float* ap = mp + HW;                      // avg plane

    float acc = sb;
    #pragma unroll
    for (int kh = 0; kh < 7; ++kh) {
        int hh = h + kh - 3;
        if (hh < 0 || hh >= HH) continue;
        int rowoff = hh * WW;
        #pragma unroll
        for (int kw = 0; kw < 7; ++kw) {
            int ww = wq + kw - 3;
            if (ww < 0 || ww >= WW) continue;
            int off = rowoff + ww;
            acc = fmaf(sw[kh * 7 + kw],      mp[off], acc);
            acc = fmaf(sw[49 + kh * 7 + kw], ap[off], acc);
        }
    }
    // hsigmoid: clip(acc+3, 0, 6)/6 == saturate((acc+3)/6)
    g_gate[idx] = __saturatef((acc + 3.0f) * (1.0f / 6.0f));
}

// ---------------------------------------------------------------------------
// Kernel 3: out = x * gate (gate broadcast over channels). float4 streaming.
// ---------------------------------------------------------------------------
__global__ void __launch_bounds__(256) apply_kernel(const float* __restrict__ x,
                                                    float* __restrict__ out) {
    size_t i4 = (size_t)blockIdx.x * blockDim.x + threadIdx.x; // 0 .. B*C*HW4-1 (16M)
    int b   = (int)(i4 >> 20);            // / (C*HW4) = / 2^20
    int hw4 = (int)(i4 & (HW4 - 1));

    float4 g = reinterpret_cast<const float4*>(g_gate)[b * HW4 + hw4];
    float4 v = reinterpret_cast<const float4*>(x)[i4];
    float4 o;
    o.x = v.x * g.x;  o.y = v.y * g.y;
    o.z = v.z * g.z;  o.w = v.w * g.w;
    reinterpret_cast<float4*>(out)[i4] = o;
}

// ---------------------------------------------------------------------------
extern "C" void kernel_launch(void* const* d_in, const int* in_sizes, int n_in,
                              void* d_out, int out_size) {
    const float* x      = (const float*)d_in[0];   // [16,256,128,128]
    const float* conv_w = (const float*)d_in[1];   // [1,2,7,7]
    const float* conv_b = (const float*)d_in[2];   // [1]
    float* out = (float*)d_out;

    // Kernel 1: B*HW4 = 65536 threads
    reduce_kernel<<<(BB * HW4) / 256, 256>>>(x);

    // Kernel 2: B*HW = 262144 threads
    conv_kernel<<<(BB * HW) / 256, 256>>>(conv_w, conv_b);

    // Kernel 3: B*C*HW4 = 16777216 threads
    apply_kernel<<<(BB * CC * HW4) / 256, 256>>>(x, out);
}